// round 9
// baseline (speedup 1.0000x reference)
#include <cuda_runtime.h>
#include <cstdint>

#define NB 16
#define NL 1024
#define ND 512
#define NH 256
#define NK 4
#define NROWS (NB * NL)   // 16384

// ---------------- scratch (static device globals; no allocs) ----------------
__device__ float    g_sel [NROWS * NK];   // softmax selections     (256 KB)
__device__ float    g_uin [NROWS * NH];   // x @ W_B^T              (16 MB)
__device__ float    g_invn[NROWS * NH];   // RAW Lp sums (norm^1.2) (16 MB)
__device__ unsigned g_flag[16][NB][NL];   // [jslice16][batch][t]   (1 MB)

// ---------------- helpers ----------------------------------------------------
__device__ __forceinline__ float fast_lg2(float x) {
    float r; asm("lg2.approx.f32 %0, %1;" : "=f"(r) : "f"(x)); return r;
}
__device__ __forceinline__ float fast_ex2(float x) {
    float r; asm("ex2.approx.f32 %0, %1;" : "=f"(r) : "f"(x)); return r;
}
__device__ __forceinline__ uint32_t smem_u32(const void* p) {
    uint32_t a;
    asm("{ .reg .u64 t; cvta.to.shared.u64 t, %1; cvt.u32.u64 %0, t; }"
        : "=r"(a) : "l"(p));
    return a;
}
__device__ __forceinline__ uint32_t mapa_u32(uint32_t a, uint32_t r) {
    uint32_t d;
    asm("mapa.shared::cluster.u32 %0, %1, %2;" : "=r"(d) : "r"(a), "r"(r));
    return d;
}
__device__ __forceinline__ void mbar_wait(uint32_t mb, uint32_t ph) {
    asm volatile(
        "{\n\t.reg .pred p;\n"
        "WL%=:\n\t"
        "mbarrier.try_wait.parity.acquire.cluster.shared::cta.b64 p, [%0], %1;\n\t"
        "@!p bra WL%=;\n\t}"
        :: "r"(mb), "r"(ph) : "memory");
}
__device__ __forceinline__ unsigned ld_acq(const unsigned* p) {
    unsigned v;
    asm volatile("ld.acquire.gpu.global.u32 %0, [%1];" : "=r"(v) : "l"(p) : "memory");
    return v;
}
__device__ __forceinline__ void st_rel(unsigned* p, unsigned v) {
    asm volatile("st.release.gpu.global.u32 [%0], %1;" :: "l"(p), "r"(v) : "memory");
}

// ---------------- kernel 0: clear flags (graph replays!) ---------------------
__global__ void clear_kernel() {
    ((unsigned*)g_flag)[blockIdx.x * blockDim.x + threadIdx.x] = 0u;
}

// ---------------- kernel 1: selection logits + softmax ----------------------
__global__ __launch_bounds__(256) void sel_kernel(
    const float* __restrict__ x, const float* __restrict__ Wsel,
    const float* __restrict__ bsel)
{
    __shared__ float Ws[NK * ND];
    for (int i = threadIdx.x; i < NK * ND; i += blockDim.x) Ws[i] = Wsel[i];
    __syncthreads();

    int w = threadIdx.x >> 5, l = threadIdx.x & 31;
    int row = blockIdx.x * 8 + w;
    const float* xr = x + row * ND;

    float p0 = 0.f, p1 = 0.f, p2 = 0.f, p3 = 0.f;
    for (int d = l; d < ND; d += 32) {
        float xv = xr[d];
        p0 += xv * Ws[d];
        p1 += xv * Ws[ND + d];
        p2 += xv * Ws[2 * ND + d];
        p3 += xv * Ws[3 * ND + d];
    }
#pragma unroll
    for (int o = 16; o > 0; o >>= 1) {
        p0 += __shfl_xor_sync(0xffffffffu, p0, o);
        p1 += __shfl_xor_sync(0xffffffffu, p1, o);
        p2 += __shfl_xor_sync(0xffffffffu, p2, o);
        p3 += __shfl_xor_sync(0xffffffffu, p3, o);
    }
    if (l == 0) {
        float l0 = p0 + bsel[0], l1 = p1 + bsel[1], l2 = p2 + bsel[2], l3 = p3 + bsel[3];
        float m = fmaxf(fmaxf(l0, l1), fmaxf(l2, l3));
        float e0 = __expf(l0 - m), e1 = __expf(l1 - m), e2 = __expf(l2 - m), e3 = __expf(l3 - m);
        float inv = 1.0f / (e0 + e1 + e2 + e3);
        float4 out = make_float4(e0 * inv, e1 * inv, e2 * inv, e3 * inv);
        *reinterpret_cast<float4*>(&g_sel[row * NK]) = out;
    }
}

// ---------------- kernel 2: u = x @ W_B^T  (M=16384, N=256, K=512) ----------
__global__ __launch_bounds__(256) void uin_kernel(
    const float* __restrict__ X, const float* __restrict__ Wb)
{
    __shared__ float Xs[16][64];
    __shared__ float Wt[16][64];
    int m0 = blockIdx.y * 64;
    int n0 = blockIdx.x * 64;
    int tid = threadIdx.x;
    int tx = tid & 15, ty = tid >> 4;
    int lr = tid >> 2, lq = tid & 3;

    float acc[4][4];
#pragma unroll
    for (int r = 0; r < 4; r++)
#pragma unroll
        for (int c = 0; c < 4; c++) acc[r][c] = 0.f;

    for (int k0 = 0; k0 < ND; k0 += 16) {
        float4 xv = *reinterpret_cast<const float4*>(&X [(m0 + lr) * ND + k0 + lq * 4]);
        float4 wv = *reinterpret_cast<const float4*>(&Wb[(n0 + lr) * ND + k0 + lq * 4]);
        __syncthreads();
        Xs[lq * 4 + 0][lr] = xv.x; Xs[lq * 4 + 1][lr] = xv.y;
        Xs[lq * 4 + 2][lr] = xv.z; Xs[lq * 4 + 3][lr] = xv.w;
        Wt[lq * 4 + 0][lr] = wv.x; Wt[lq * 4 + 1][lr] = wv.y;
        Wt[lq * 4 + 2][lr] = wv.z; Wt[lq * 4 + 3][lr] = wv.w;
        __syncthreads();
#pragma unroll
        for (int kk = 0; kk < 16; kk++) {
            float4 a = *reinterpret_cast<const float4*>(&Xs[kk][ty * 4]);
            float4 b = *reinterpret_cast<const float4*>(&Wt[kk][tx * 4]);
            acc[0][0] += a.x * b.x; acc[0][1] += a.x * b.y; acc[0][2] += a.x * b.z; acc[0][3] += a.x * b.w;
            acc[1][0] += a.y * b.x; acc[1][1] += a.y * b.y; acc[1][2] += a.y * b.z; acc[1][3] += a.y * b.w;
            acc[2][0] += a.z * b.x; acc[2][1] += a.z * b.y; acc[2][2] += a.z * b.z; acc[2][3] += a.z * b.w;
            acc[3][0] += a.w * b.x; acc[3][1] += a.w * b.y; acc[3][2] += a.w * b.z; acc[3][3] += a.w * b.w;
        }
    }
#pragma unroll
    for (int r = 0; r < 4; r++) {
        float4 o = make_float4(acc[r][0], acc[r][1], acc[r][2], acc[r][3]);
        *reinterpret_cast<float4*>(&g_uin[(m0 + ty * 4 + r) * NH + n0 + tx * 4]) = o;
    }
}

// ---------------- kernel 3: MEGA — scan (64 CTAs) + norm producers (80) -----
// Grid 144 CTAs, 18 clusters of 8, 1 CTA/SM (all wave-1 resident).
// blockIdx < 64: scan role (R7 protocol, unchanged) + flag-gated invn loads.
//   g_invn now holds RAW Lp sums; warp0 applies x^(-1/1.2) after load.
// blockIdx >= 64: norm producer. CTA (s = id&15, k = id>>4): j-slice
//   [16s,16s+16), t-stripe t ≡ k (mod 5), all 16 batches per t. Warp w owns
//   j=16s+w; lane l sums i = l+32r (r<8) in registers. After a stripe-step:
//   __syncthreads -> st.release g_flag[s][b][t]=1 for all b.
// Pacing: producer 1638 cyc/t < scan ~1700 cyc/t.
__global__ __launch_bounds__(512, 1) __cluster_dims__(8, 1, 1)
void mega_kernel(const float* __restrict__ A, float* __restrict__ out)
{
    int tid = threadIdx.x;

    if (blockIdx.x >= 64) {
        // ================= norm producer role =================
        int id = blockIdx.x - 64;        // 0..79
        int s  = id & 15;                // j-slice
        int k  = id >> 4;                // t-stripe 0..4
        int w = tid >> 5, l = tid & 31;
        int j = s * 16 + w;

        float4 Ar[8];
#pragma unroll
        for (int r = 0; r < 8; r++)
            Ar[r] = reinterpret_cast<const float4*>(A)[(l + 32 * r) * NH + j];

        for (int t = k; t < NL; t += 5) {
            for (int b = 0; b < NB; b++) {
                int row = b * NL + t;
                float4 s4 = __ldg(reinterpret_cast<const float4*>(&g_sel[row * NK]));
                float acc = 0.f;
#pragma unroll
                for (int r = 0; r < 8; r++) {
                    float a = fmaf(s4.x, Ar[r].x, fmaf(s4.y, Ar[r].y,
                              fmaf(s4.z, Ar[r].z, s4.w * Ar[r].w)));
                    acc += fast_ex2(0.6f * fast_lg2(a * a));
                }
#pragma unroll
                for (int o = 16; o > 0; o >>= 1)
                    acc += __shfl_xor_sync(0xffffffffu, acc, o);
                if (l == 0)
                    g_invn[row * NH + j] = acc;          // RAW Lp sum
            }
            __syncthreads();                              // all j of this slice done
            if (tid < NB)
                st_rel(&g_flag[s][tid][t], 1u);
        }
        return;
    }

    // ================= scan role (R7 protocol) =================
    __shared__ float y_sm[2][32];
    __shared__ float pbuf[2][2][8][32];                     // [parity][batch][src][row]
    __shared__ __align__(8) unsigned long long mbar[2][2];  // [parity][batch]

    uint32_t rank;
    asm("mov.u32 %0, %%cluster_ctarank;" : "=r"(rank));
    int c = blockIdx.x >> 3;                 // cluster id -> batches 2c, 2c+1
    int jbase = (int)rank * 32;
    int i = tid >> 1, half = tid & 1;
    const float ninv = -1.0f / 1.2f;

    float4 Areg[16];
#pragma unroll
    for (int q = 0; q < 16; q++)
        Areg[q] = reinterpret_cast<const float4*>(A)[i * NH + jbase + half * 16 + q];

    uint32_t mbar_s = smem_u32(mbar);
    if (tid == 0) {
#pragma unroll
        for (int m = 0; m < 4; m++)
            asm volatile("mbarrier.init.shared.b64 [%0], 1;"
                         :: "r"(mbar_s + m * 8) : "memory");
    }
    __syncthreads();
    if (tid == 0) {
#pragma unroll
        for (int m = 0; m < 4; m++)
            asm volatile("mbarrier.arrive.expect_tx.shared.b64 _, [%0], 1024;"
                         :: "r"(mbar_s + m * 8) : "memory");
    }
    __syncthreads();
    asm volatile("barrier.cluster.arrive.aligned;" ::: "memory");
    asm volatile("barrier.cluster.wait.aligned;"  ::: "memory");

    uint32_t dst = (uint32_t)(i >> 5);
    uint32_t lbase = smem_u32(pbuf) + (rank * 32u + (uint32_t)(i & 31)) * 4u;
    uint32_t raddr = mapa_u32(lbase, dst);   // parity stride 2048B, batch stride 1024B
    uint32_t rmbar = mapa_u32(mbar_s, dst);  // parity stride 16B,   batch stride 8B

    const int row0base = (2 * c) * NL;
    const int row1base = (2 * c + 1) * NL;

    float4 s0 = __ldg(reinterpret_cast<const float4*>(&g_sel[row0base * NK]));
    float4 s1 = __ldg(reinterpret_cast<const float4*>(&g_sel[row1base * NK]));
    float inv0 = 0.f, u0 = 0.f, h0 = 0.f;
    float inv1 = 0.f, u1 = 0.f, h1 = 0.f;
    if (tid < 32) {
        // wait for t=0 flags (lanes 0..3: ss = 2*rank + (lane&1), bb = 2c + (lane>>1))
        if (tid < 4) {
            const unsigned* f = &g_flag[2 * rank + (tid & 1)][2 * c + (tid >> 1)][0];
            while (!ld_acq(f)) {}
        }
        __syncwarp();
        inv0 = fast_ex2(fast_lg2(g_invn[row0base * NH + jbase + tid]) * ninv);
        inv1 = fast_ex2(fast_lg2(g_invn[row1base * NH + jbase + tid]) * ninv);
        u0   = __ldg(&g_uin[row0base * NH + jbase + tid]);
        u1   = __ldg(&g_uin[row1base * NH + jbase + tid]);
    }

    float amix0[16], amix1[16];
#pragma unroll
    for (int q = 0; q < 16; q++) {
        amix0[q] = fmaf(s0.x, Areg[q].x, fmaf(s0.y, Areg[q].y,
                   fmaf(s0.z, Areg[q].z, s0.w * Areg[q].w)));
        amix1[q] = fmaf(s1.x, Areg[q].x, fmaf(s1.y, Areg[q].y,
                   fmaf(s1.z, Areg[q].z, s1.w * Areg[q].w)));
    }

    for (int t = 0; t < NL; t++) {
        const int row0 = row0base + t;
        const int row1 = row1base + t;
        if (tid < 32) {
            y_sm[0][tid] = h0 * inv0;
            y_sm[1][tid] = h1 * inv1;
        }
        __syncthreads();

        const int d = (t < NL - 1) ? 1 : 0;
        const int tn = (t < NL - 1) ? t + 1 : t;
        float4 s_n0 = __ldg(reinterpret_cast<const float4*>(&g_sel[(row0 + d) * NK]));
        float4 s_n1 = __ldg(reinterpret_cast<const float4*>(&g_sel[(row1 + d) * NK]));
        float inv_n0 = 0.f, u_n0 = 0.f, inv_n1 = 0.f, u_n1 = 0.f;
        if (tid < 32) {
            if (tid < 4) {
                const unsigned* f = &g_flag[2 * rank + (tid & 1)][2 * c + (tid >> 1)][tn];
                while (!ld_acq(f)) {}
            }
            __syncwarp();
            inv_n0 = fast_ex2(fast_lg2(g_invn[(row0 + d) * NH + jbase + tid]) * ninv);
            inv_n1 = fast_ex2(fast_lg2(g_invn[(row1 + d) * NH + jbase + tid]) * ninv);
            u_n0   = __ldg(&g_uin[(row0 + d) * NH + jbase + tid]);
            u_n1   = __ldg(&g_uin[(row1 + d) * NH + jbase + tid]);
        }

        const uint32_t poff = (uint32_t)(t & 1);

        // ---- batch 0: matvec + store ----
        {
            float a0 = 0.f, a1 = 0.f;
#pragma unroll
            for (int q = 0; q < 16; q += 2) {
                a0 = fmaf(amix0[q],     y_sm[0][half * 16 + q],     a0);
                a1 = fmaf(amix0[q + 1], y_sm[0][half * 16 + q + 1], a1);
            }
            float acc = a0 + a1;
            acc += __shfl_xor_sync(0xffffffffu, acc, 1);
            if (half == 0) {
                asm volatile(
                    "st.async.shared::cluster.mbarrier::complete_tx::bytes.b32 [%0], %1, [%2];"
                    :: "r"(raddr + poff * 2048u), "r"(__float_as_uint(acc)),
                       "r"(rmbar + poff * 16u) : "memory");
            }
        }
        // ---- batch 1: matvec + store (hides batch0 flight) ----
        {
            float a0 = 0.f, a1 = 0.f;
#pragma unroll
            for (int q = 0; q < 16; q += 2) {
                a0 = fmaf(amix1[q],     y_sm[1][half * 16 + q],     a0);
                a1 = fmaf(amix1[q + 1], y_sm[1][half * 16 + q + 1], a1);
            }
            float acc = a0 + a1;
            acc += __shfl_xor_sync(0xffffffffu, acc, 1);
            if (half == 0) {
                asm volatile(
                    "st.async.shared::cluster.mbarrier::complete_tx::bytes.b32 [%0], %1, [%2];"
                    :: "r"(raddr + poff * 2048u + 1024u), "r"(__float_as_uint(acc)),
                       "r"(rmbar + poff * 16u + 8u) : "memory");
            }
        }

        // hide DSMEM flight: amix for t+1, both batches
#pragma unroll
        for (int q = 0; q < 16; q++) {
            amix0[q] = fmaf(s_n0.x, Areg[q].x, fmaf(s_n0.y, Areg[q].y,
                       fmaf(s_n0.z, Areg[q].z, s_n0.w * Areg[q].w)));
            amix1[q] = fmaf(s_n1.x, Areg[q].x, fmaf(s_n1.y, Areg[q].y,
                       fmaf(s_n1.z, Areg[q].z, s_n1.w * Areg[q].w)));
        }

        if (tid < 32) {
            const uint32_t ph = (uint32_t)((t >> 1) & 1);
            // ---- batch 0 tail ----
            mbar_wait(mbar_s + poff * 16u, ph);
            if (tid == 0 && t + 2 < NL)
                asm volatile("mbarrier.arrive.expect_tx.shared.b64 _, [%0], 1024;"
                             :: "r"(mbar_s + poff * 16u) : "memory");
            {
                const float* pb = &pbuf[poff][0][0][tid];
                float b0 = pb[0]   + pb[32];
                float b1 = pb[64]  + pb[96];
                float b2 = pb[128] + pb[160];
                float b3 = pb[192] + pb[224];
                float hv = u0 + ((b0 + b1) + (b2 + b3));
                out[row0 * NH + jbase + tid] = hv;
                h0 = hv; inv0 = inv_n0; u0 = u_n0;
            }
            // ---- batch 1 tail ----
            mbar_wait(mbar_s + poff * 16u + 8u, ph);
            if (tid == 0 && t + 2 < NL)
                asm volatile("mbarrier.arrive.expect_tx.shared.b64 _, [%0], 1024;"
                             :: "r"(mbar_s + poff * 16u + 8u) : "memory");
            {
                const float* pb = &pbuf[poff][1][0][tid];
                float b0 = pb[0]   + pb[32];
                float b1 = pb[64]  + pb[96];
                float b2 = pb[128] + pb[160];
                float b3 = pb[192] + pb[224];
                float hv = u1 + ((b0 + b1) + (b2 + b3));
                out[row1 * NH + jbase + tid] = hv;
                h1 = hv; inv1 = inv_n1; u1 = u_n1;
            }
        }
    }

    asm volatile("barrier.cluster.arrive.aligned;" ::: "memory");
    asm volatile("barrier.cluster.wait.aligned;"  ::: "memory");
}

// ---------------- launch ----------------------------------------------------
extern "C" void kernel_launch(void* const* d_in, const int* in_sizes, int n_in,
                              void* d_out, int out_size)
{
    const float* x     = (const float*)d_in[0];   // (16,1024,512)
    const float* Wsel  = (const float*)d_in[1];   // (4,512)
    const float* bsel  = (const float*)d_in[2];   // (4,)
    const float* Wb    = (const float*)d_in[3];   // (256,512)
    const float* Adict = (const float*)d_in[4];   // (256,256,4)
    float* out = (float*)d_out;                   // (16,1024,256)

    clear_kernel<<<512, 512>>>();                 // 16*16*1024 flags = 512*512
    sel_kernel<<<NROWS / 8, 256>>>(x, Wsel, bsel);
    uin_kernel<<<dim3(NH / 64, NROWS / 64), 256>>>(x, Wb);
    mega_kernel<<<144, 512>>>(Adict, out);        // 64 scan + 80 norm, 18 clusters
}

// round 10
// speedup vs baseline: 1.0373x; 1.0373x over previous
#include <cuda_runtime.h>
#include <cstdint>

#define NB 16
#define NL 1024
#define ND 512
#define NH 256
#define NK 4
#define NROWS (NB * NL)   // 16384

// ---------------- scratch (static device globals; no allocs) ----------------
__device__ float    g_sel  [NROWS * NK];  // softmax selections     (256 KB)
__device__ float    g_uin  [NROWS * NH];  // x @ W_B^T              (16 MB)
__device__ float    g_invn [NROWS * NH];  // RAW Lp sums            (16 MB)
__device__ unsigned g_flagJ[NH][NL];      // per-(j,t) ready flags  (1 MB)

// ---------------- helpers ----------------------------------------------------
__device__ __forceinline__ float fast_lg2(float x) {
    float r; asm("lg2.approx.f32 %0, %1;" : "=f"(r) : "f"(x)); return r;
}
__device__ __forceinline__ float fast_ex2(float x) {
    float r; asm("ex2.approx.f32 %0, %1;" : "=f"(r) : "f"(x)); return r;
}
__device__ __forceinline__ uint32_t smem_u32(const void* p) {
    uint32_t a;
    asm("{ .reg .u64 t; cvta.to.shared.u64 t, %1; cvt.u32.u64 %0, t; }"
        : "=r"(a) : "l"(p));
    return a;
}
__device__ __forceinline__ uint32_t mapa_u32(uint32_t a, uint32_t r) {
    uint32_t d;
    asm("mapa.shared::cluster.u32 %0, %1, %2;" : "=r"(d) : "r"(a), "r"(r));
    return d;
}
__device__ __forceinline__ void mbar_wait(uint32_t mb, uint32_t ph) {
    asm volatile(
        "{\n\t.reg .pred p;\n"
        "WL%=:\n\t"
        "mbarrier.try_wait.parity.acquire.cluster.shared::cta.b64 p, [%0], %1;\n\t"
        "@!p bra WL%=;\n\t}"
        :: "r"(mb), "r"(ph) : "memory");
}
__device__ __forceinline__ unsigned ld_acq(const unsigned* p) {
    unsigned v;
    asm volatile("ld.acquire.gpu.global.u32 %0, [%1];" : "=r"(v) : "l"(p) : "memory");
    return v;
}
__device__ __forceinline__ void st_rel(unsigned* p, unsigned v) {
    asm volatile("st.release.gpu.global.u32 [%0], %1;" :: "l"(p), "r"(v) : "memory");
}

// ---------------- kernel 0: clear flags (graph replays!) ---------------------
__global__ void clear_kernel() {
    ((unsigned*)g_flagJ)[blockIdx.x * blockDim.x + threadIdx.x] = 0u;
}

// ---------------- kernel 1: selection logits + softmax ----------------------
__global__ __launch_bounds__(256) void sel_kernel(
    const float* __restrict__ x, const float* __restrict__ Wsel,
    const float* __restrict__ bsel)
{
    __shared__ float Ws[NK * ND];
    for (int i = threadIdx.x; i < NK * ND; i += blockDim.x) Ws[i] = Wsel[i];
    __syncthreads();

    int w = threadIdx.x >> 5, l = threadIdx.x & 31;
    int row = blockIdx.x * 8 + w;
    const float* xr = x + row * ND;

    float p0 = 0.f, p1 = 0.f, p2 = 0.f, p3 = 0.f;
    for (int d = l; d < ND; d += 32) {
        float xv = xr[d];
        p0 += xv * Ws[d];
        p1 += xv * Ws[ND + d];
        p2 += xv * Ws[2 * ND + d];
        p3 += xv * Ws[3 * ND + d];
    }
#pragma unroll
    for (int o = 16; o > 0; o >>= 1) {
        p0 += __shfl_xor_sync(0xffffffffu, p0, o);
        p1 += __shfl_xor_sync(0xffffffffu, p1, o);
        p2 += __shfl_xor_sync(0xffffffffu, p2, o);
        p3 += __shfl_xor_sync(0xffffffffu, p3, o);
    }
    if (l == 0) {
        float l0 = p0 + bsel[0], l1 = p1 + bsel[1], l2 = p2 + bsel[2], l3 = p3 + bsel[3];
        float m = fmaxf(fmaxf(l0, l1), fmaxf(l2, l3));
        float e0 = __expf(l0 - m), e1 = __expf(l1 - m), e2 = __expf(l2 - m), e3 = __expf(l3 - m);
        float inv = 1.0f / (e0 + e1 + e2 + e3);
        float4 out = make_float4(e0 * inv, e1 * inv, e2 * inv, e3 * inv);
        *reinterpret_cast<float4*>(&g_sel[row * NK]) = out;
    }
}

// ---------------- kernel 2: u = x @ W_B^T  (M=16384, N=256, K=512) ----------
__global__ __launch_bounds__(256) void uin_kernel(
    const float* __restrict__ X, const float* __restrict__ Wb)
{
    __shared__ float Xs[16][64];
    __shared__ float Wt[16][64];
    int m0 = blockIdx.y * 64;
    int n0 = blockIdx.x * 64;
    int tid = threadIdx.x;
    int tx = tid & 15, ty = tid >> 4;
    int lr = tid >> 2, lq = tid & 3;

    float acc[4][4];
#pragma unroll
    for (int r = 0; r < 4; r++)
#pragma unroll
        for (int c = 0; c < 4; c++) acc[r][c] = 0.f;

    for (int k0 = 0; k0 < ND; k0 += 16) {
        float4 xv = *reinterpret_cast<const float4*>(&X [(m0 + lr) * ND + k0 + lq * 4]);
        float4 wv = *reinterpret_cast<const float4*>(&Wb[(n0 + lr) * ND + k0 + lq * 4]);
        __syncthreads();
        Xs[lq * 4 + 0][lr] = xv.x; Xs[lq * 4 + 1][lr] = xv.y;
        Xs[lq * 4 + 2][lr] = xv.z; Xs[lq * 4 + 3][lr] = xv.w;
        Wt[lq * 4 + 0][lr] = wv.x; Wt[lq * 4 + 1][lr] = wv.y;
        Wt[lq * 4 + 2][lr] = wv.z; Wt[lq * 4 + 3][lr] = wv.w;
        __syncthreads();
#pragma unroll
        for (int kk = 0; kk < 16; kk++) {
            float4 a = *reinterpret_cast<const float4*>(&Xs[kk][ty * 4]);
            float4 b = *reinterpret_cast<const float4*>(&Wt[kk][tx * 4]);
            acc[0][0] += a.x * b.x; acc[0][1] += a.x * b.y; acc[0][2] += a.x * b.z; acc[0][3] += a.x * b.w;
            acc[1][0] += a.y * b.x; acc[1][1] += a.y * b.y; acc[1][2] += a.y * b.z; acc[1][3] += a.y * b.w;
            acc[2][0] += a.z * b.x; acc[2][1] += a.z * b.y; acc[2][2] += a.z * b.z; acc[2][3] += a.z * b.w;
            acc[3][0] += a.w * b.x; acc[3][1] += a.w * b.y; acc[3][2] += a.w * b.z; acc[3][3] += a.w * b.w;
        }
    }
#pragma unroll
    for (int r = 0; r < 4; r++) {
        float4 o = make_float4(acc[r][0], acc[r][1], acc[r][2], acc[r][3]);
        *reinterpret_cast<float4*>(&g_uin[(m0 + ty * 4 + r) * NH + n0 + tx * 4]) = o;
    }
}

// ---------------- kernel 3: MEGA — scan (64 CTAs) + norm producers (80) -----
// blockIdx < 64: scan role, R7 protocol; invn prefetch gated on per-(j,t)
//   flags inside warp0's tail (overlaps mbarrier wait); applies x^(-1/1.2).
// blockIdx >= 64: producer (s = id&15 -> j-slice of 16, k = id>>4 -> t-stripe
//   mod 5). Warp w owns j = 16s+w. NO syncthreads; 2-batch unrolled inner
//   loop (independent MUFU chains); lane0 st.release g_flagJ[j][t] after all
//   16 batches of (j,t).
__global__ __launch_bounds__(512, 1) __cluster_dims__(8, 1, 1)
void mega_kernel(const float* __restrict__ A, float* __restrict__ out)
{
    int tid = threadIdx.x;

    if (blockIdx.x >= 64) {
        // ================= norm producer role =================
        int id = blockIdx.x - 64;        // 0..79
        int s  = id & 15;                // j-slice
        int k  = id >> 4;                // t-stripe 0..4
        int w = tid >> 5, l = tid & 31;
        int j = s * 16 + w;

        float4 Ar[8];
#pragma unroll
        for (int r = 0; r < 8; r++)
            Ar[r] = reinterpret_cast<const float4*>(A)[(l + 32 * r) * NH + j];

        for (int t = k; t < NL; t += 5) {
#pragma unroll 1
            for (int b = 0; b < NB; b += 2) {
                int rowA = b * NL + t;
                int rowB = rowA + NL;
                float4 sA = __ldg(reinterpret_cast<const float4*>(&g_sel[rowA * NK]));
                float4 sB = __ldg(reinterpret_cast<const float4*>(&g_sel[rowB * NK]));
                float accA = 0.f, accB = 0.f;
#pragma unroll
                for (int r = 0; r < 8; r++) {
                    float a = fmaf(sA.x, Ar[r].x, fmaf(sA.y, Ar[r].y,
                              fmaf(sA.z, Ar[r].z, sA.w * Ar[r].w)));
                    float bv = fmaf(sB.x, Ar[r].x, fmaf(sB.y, Ar[r].y,
                               fmaf(sB.z, Ar[r].z, sB.w * Ar[r].w)));
                    accA += fast_ex2(0.6f * fast_lg2(a * a));
                    accB += fast_ex2(0.6f * fast_lg2(bv * bv));
                }
#pragma unroll
                for (int o = 16; o > 0; o >>= 1) {
                    accA += __shfl_xor_sync(0xffffffffu, accA, o);
                    accB += __shfl_xor_sync(0xffffffffu, accB, o);
                }
                if (l == 0) {
                    g_invn[rowA * NH + j] = accA;   // RAW Lp sums
                    g_invn[rowB * NH + j] = accB;
                }
            }
            if (l == 0)
                st_rel(&g_flagJ[j][t], 1u);         // release orders invn stores
        }
        return;
    }

    // ================= scan role (R7 protocol + gated invn) =================
    __shared__ float y_sm[2][32];
    __shared__ float pbuf[2][2][8][32];                     // [parity][batch][src][row]
    __shared__ __align__(8) unsigned long long mbar[2][2];  // [parity][batch]

    uint32_t rank;
    asm("mov.u32 %0, %%cluster_ctarank;" : "=r"(rank));
    int c = blockIdx.x >> 3;                 // cluster id -> batches 2c, 2c+1
    int jbase = (int)rank * 32;
    int i = tid >> 1, half = tid & 1;
    const float ninv = -1.0f / 1.2f;

    float4 Areg[16];
#pragma unroll
    for (int q = 0; q < 16; q++)
        Areg[q] = reinterpret_cast<const float4*>(A)[i * NH + jbase + half * 16 + q];

    uint32_t mbar_s = smem_u32(mbar);
    if (tid == 0) {
#pragma unroll
        for (int m = 0; m < 4; m++)
            asm volatile("mbarrier.init.shared.b64 [%0], 1;"
                         :: "r"(mbar_s + m * 8) : "memory");
    }
    __syncthreads();
    if (tid == 0) {
#pragma unroll
        for (int m = 0; m < 4; m++)
            asm volatile("mbarrier.arrive.expect_tx.shared.b64 _, [%0], 1024;"
                         :: "r"(mbar_s + m * 8) : "memory");
    }
    __syncthreads();
    asm volatile("barrier.cluster.arrive.aligned;" ::: "memory");
    asm volatile("barrier.cluster.wait.aligned;"  ::: "memory");

    uint32_t dst = (uint32_t)(i >> 5);
    uint32_t lbase = smem_u32(pbuf) + (rank * 32u + (uint32_t)(i & 31)) * 4u;
    uint32_t raddr = mapa_u32(lbase, dst);   // parity stride 2048B, batch stride 1024B
    uint32_t rmbar = mapa_u32(mbar_s, dst);  // parity stride 16B,   batch stride 8B

    const int row0base = (2 * c) * NL;
    const int row1base = (2 * c + 1) * NL;

    float4 s0 = __ldg(reinterpret_cast<const float4*>(&g_sel[row0base * NK]));
    float4 s1 = __ldg(reinterpret_cast<const float4*>(&g_sel[row1base * NK]));
    float inv0 = 0.f, u0 = 0.f, h0 = 0.f;
    float inv1 = 0.f, u1 = 0.f, h1 = 0.f;
    if (tid < 32) {
        while (!ld_acq(&g_flagJ[jbase + tid][0])) { }
        float r0 = g_invn[row0base * NH + jbase + tid];
        float r1 = g_invn[row1base * NH + jbase + tid];
        inv0 = fast_ex2(fast_lg2(r0) * ninv);
        inv1 = fast_ex2(fast_lg2(r1) * ninv);
        u0   = __ldg(&g_uin[row0base * NH + jbase + tid]);
        u1   = __ldg(&g_uin[row1base * NH + jbase + tid]);
    }

    float amix0[16], amix1[16];
#pragma unroll
    for (int q = 0; q < 16; q++) {
        amix0[q] = fmaf(s0.x, Areg[q].x, fmaf(s0.y, Areg[q].y,
                   fmaf(s0.z, Areg[q].z, s0.w * Areg[q].w)));
        amix1[q] = fmaf(s1.x, Areg[q].x, fmaf(s1.y, Areg[q].y,
                   fmaf(s1.z, Areg[q].z, s1.w * Areg[q].w)));
    }

    for (int t = 0; t < NL; t++) {
        const int row0 = row0base + t;
        const int row1 = row1base + t;
        if (tid < 32) {
            y_sm[0][tid] = h0 * inv0;
            y_sm[1][tid] = h1 * inv1;
        }
        __syncthreads();

        const int d = (t < NL - 1) ? 1 : 0;
        const int tn = t + d;
        float4 s_n0 = __ldg(reinterpret_cast<const float4*>(&g_sel[(row0 + d) * NK]));
        float4 s_n1 = __ldg(reinterpret_cast<const float4*>(&g_sel[(row1 + d) * NK]));

        const uint32_t poff = (uint32_t)(t & 1);

        // ---- batch 0: matvec + store ----
        {
            float a0 = 0.f, a1 = 0.f;
#pragma unroll
            for (int q = 0; q < 16; q += 2) {
                a0 = fmaf(amix0[q],     y_sm[0][half * 16 + q],     a0);
                a1 = fmaf(amix0[q + 1], y_sm[0][half * 16 + q + 1], a1);
            }
            float acc = a0 + a1;
            acc += __shfl_xor_sync(0xffffffffu, acc, 1);
            if (half == 0) {
                asm volatile(
                    "st.async.shared::cluster.mbarrier::complete_tx::bytes.b32 [%0], %1, [%2];"
                    :: "r"(raddr + poff * 2048u), "r"(__float_as_uint(acc)),
                       "r"(rmbar + poff * 16u) : "memory");
            }
        }
        // ---- batch 1: matvec + store (hides batch0 flight) ----
        {
            float a0 = 0.f, a1 = 0.f;
#pragma unroll
            for (int q = 0; q < 16; q += 2) {
                a0 = fmaf(amix1[q],     y_sm[1][half * 16 + q],     a0);
                a1 = fmaf(amix1[q + 1], y_sm[1][half * 16 + q + 1], a1);
            }
            float acc = a0 + a1;
            acc += __shfl_xor_sync(0xffffffffu, acc, 1);
            if (half == 0) {
                asm volatile(
                    "st.async.shared::cluster.mbarrier::complete_tx::bytes.b32 [%0], %1, [%2];"
                    :: "r"(raddr + poff * 2048u + 1024u), "r"(__float_as_uint(acc)),
                       "r"(rmbar + poff * 16u + 8u) : "memory");
            }
        }

        // hide DSMEM flight: amix for t+1, both batches
#pragma unroll
        for (int q = 0; q < 16; q++) {
            amix0[q] = fmaf(s_n0.x, Areg[q].x, fmaf(s_n0.y, Areg[q].y,
                       fmaf(s_n0.z, Areg[q].z, s_n0.w * Areg[q].w)));
            amix1[q] = fmaf(s_n1.x, Areg[q].x, fmaf(s_n1.y, Areg[q].y,
                       fmaf(s_n1.z, Areg[q].z, s_n1.w * Areg[q].w)));
        }

        if (tid < 32) {
            // gated prefetch for t+1 (overlaps the mbarrier waits below)
            while (!ld_acq(&g_flagJ[jbase + tid][tn])) { }
            float r0 = g_invn[(row0 + d) * NH + jbase + tid];
            float r1 = g_invn[(row1 + d) * NH + jbase + tid];
            float u_n0 = __ldg(&g_uin[(row0 + d) * NH + jbase + tid]);
            float u_n1 = __ldg(&g_uin[(row1 + d) * NH + jbase + tid]);
            float inv_n0 = fast_ex2(fast_lg2(r0) * ninv);
            float inv_n1 = fast_ex2(fast_lg2(r1) * ninv);

            const uint32_t ph = (uint32_t)((t >> 1) & 1);
            // ---- batch 0 tail ----
            mbar_wait(mbar_s + poff * 16u, ph);
            if (tid == 0 && t + 2 < NL)
                asm volatile("mbarrier.arrive.expect_tx.shared.b64 _, [%0], 1024;"
                             :: "r"(mbar_s + poff * 16u) : "memory");
            {
                const float* pb = &pbuf[poff][0][0][tid];
                float b0 = pb[0]   + pb[32];
                float b1 = pb[64]  + pb[96];
                float b2 = pb[128] + pb[160];
                float b3 = pb[192] + pb[224];
                float hv = u0 + ((b0 + b1) + (b2 + b3));
                out[row0 * NH + jbase + tid] = hv;
                h0 = hv; inv0 = inv_n0; u0 = u_n0;
            }
            // ---- batch 1 tail ----
            mbar_wait(mbar_s + poff * 16u + 8u, ph);
            if (tid == 0 && t + 2 < NL)
                asm volatile("mbarrier.arrive.expect_tx.shared.b64 _, [%0], 1024;"
                             :: "r"(mbar_s + poff * 16u + 8u) : "memory");
            {
                const float* pb = &pbuf[poff][1][0][tid];
                float b0 = pb[0]   + pb[32];
                float b1 = pb[64]  + pb[96];
                float b2 = pb[128] + pb[160];
                float b3 = pb[192] + pb[224];
                float hv = u1 + ((b0 + b1) + (b2 + b3));
                out[row1 * NH + jbase + tid] = hv;
                h1 = hv; inv1 = inv_n1; u1 = u_n1;
            }
        }
    }

    asm volatile("barrier.cluster.arrive.aligned;" ::: "memory");
    asm volatile("barrier.cluster.wait.aligned;"  ::: "memory");
}

// ---------------- launch ----------------------------------------------------
extern "C" void kernel_launch(void* const* d_in, const int* in_sizes, int n_in,
                              void* d_out, int out_size)
{
    const float* x     = (const float*)d_in[0];   // (16,1024,512)
    const float* Wsel  = (const float*)d_in[1];   // (4,512)
    const float* bsel  = (const float*)d_in[2];   // (4,)
    const float* Wb    = (const float*)d_in[3];   // (256,512)
    const float* Adict = (const float*)d_in[4];   // (256,256,4)
    float* out = (float*)d_out;                   // (16,1024,256)

    clear_kernel<<<512, 512>>>();                 // NH*NL = 262144 flags
    sel_kernel<<<NROWS / 8, 256>>>(x, Wsel, bsel);
    uin_kernel<<<dim3(NH / 64, NROWS / 64), 256>>>(x, Wb);
    mega_kernel<<<144, 512>>>(Adict, out);        // 64 scan + 80 producers
}

// round 11
// speedup vs baseline: 1.8572x; 1.7905x over previous
#include <cuda_runtime.h>
#include <cstdint>

#define NB 16
#define NL 1024
#define ND 512
#define NH 256
#define NK 4
#define NROWS (NB * NL)   // 16384

// ---------------- scratch (static device globals; no allocs) ----------------
__device__ float g_sel [NROWS * NK];     // softmax selections     (256 KB)
__device__ float g_uin [NROWS * NH];     // x @ W_B^T              (16 MB)
__device__ float g_invn[NROWS * NH];     // 1/norm per (row, j)    (16 MB)

// ---------------- helpers ----------------------------------------------------
__device__ __forceinline__ float fast_lg2(float x) {
    float r; asm("lg2.approx.f32 %0, %1;" : "=f"(r) : "f"(x)); return r;
}
__device__ __forceinline__ float fast_ex2(float x) {
    float r; asm("ex2.approx.f32 %0, %1;" : "=f"(r) : "f"(x)); return r;
}
__device__ __forceinline__ uint32_t smem_u32(const void* p) {
    uint32_t a;
    asm("{ .reg .u64 t; cvta.to.shared.u64 t, %1; cvt.u32.u64 %0, t; }"
        : "=r"(a) : "l"(p));
    return a;
}
__device__ __forceinline__ uint32_t mapa_u32(uint32_t a, uint32_t r) {
    uint32_t d;
    asm("mapa.shared::cluster.u32 %0, %1, %2;" : "=r"(d) : "r"(a), "r"(r));
    return d;
}
__device__ __forceinline__ void mbar_wait(uint32_t mb, uint32_t ph) {
    asm volatile(
        "{\n\t.reg .pred p;\n"
        "WL%=:\n\t"
        "mbarrier.try_wait.parity.acquire.cluster.shared::cta.b64 p, [%0], %1;\n\t"
        "@!p bra WL%=;\n\t}"
        :: "r"(mb), "r"(ph) : "memory");
}

// ---------------- kernel 1: selection logits + softmax ----------------------
__global__ __launch_bounds__(256) void sel_kernel(
    const float* __restrict__ x, const float* __restrict__ Wsel,
    const float* __restrict__ bsel)
{
    __shared__ float Ws[NK * ND];
    for (int i = threadIdx.x; i < NK * ND; i += blockDim.x) Ws[i] = Wsel[i];
    __syncthreads();

    int w = threadIdx.x >> 5, l = threadIdx.x & 31;
    int row = blockIdx.x * 8 + w;
    const float* xr = x + row * ND;

    float p0 = 0.f, p1 = 0.f, p2 = 0.f, p3 = 0.f;
    for (int d = l; d < ND; d += 32) {
        float xv = xr[d];
        p0 += xv * Ws[d];
        p1 += xv * Ws[ND + d];
        p2 += xv * Ws[2 * ND + d];
        p3 += xv * Ws[3 * ND + d];
    }
#pragma unroll
    for (int o = 16; o > 0; o >>= 1) {
        p0 += __shfl_xor_sync(0xffffffffu, p0, o);
        p1 += __shfl_xor_sync(0xffffffffu, p1, o);
        p2 += __shfl_xor_sync(0xffffffffu, p2, o);
        p3 += __shfl_xor_sync(0xffffffffu, p3, o);
    }
    if (l == 0) {
        float l0 = p0 + bsel[0], l1 = p1 + bsel[1], l2 = p2 + bsel[2], l3 = p3 + bsel[3];
        float m = fmaxf(fmaxf(l0, l1), fmaxf(l2, l3));
        float e0 = __expf(l0 - m), e1 = __expf(l1 - m), e2 = __expf(l2 - m), e3 = __expf(l3 - m);
        float inv = 1.0f / (e0 + e1 + e2 + e3);
        float4 out = make_float4(e0 * inv, e1 * inv, e2 * inv, e3 * inv);
        *reinterpret_cast<float4*>(&g_sel[row * NK]) = out;
    }
}

// ---------------- kernel 2: u = x @ W_B^T  v2: 128x128 tile, 8x8/thread -----
__global__ __launch_bounds__(256, 2) void uin_kernel(
    const float* __restrict__ X, const float* __restrict__ Wb)
{
    __shared__ float Xs[16][128];
    __shared__ float Wt[16][128];
    int m0 = blockIdx.x * 128;         // 128 M-tiles
    int n0 = blockIdx.y * 128;         // 2 N-tiles
    int tid = threadIdx.x;
    int tx = tid & 15, ty = tid >> 4;  // 16x16 thread grid, 8x8 each
    int lr = tid >> 2, lq = tid & 3;   // loader: row 0..63, k-quad 0..3

    float acc[8][8];
#pragma unroll
    for (int r = 0; r < 8; r++)
#pragma unroll
        for (int c = 0; c < 8; c++) acc[r][c] = 0.f;

    for (int k0 = 0; k0 < ND; k0 += 16) {
        float4 x0 = *reinterpret_cast<const float4*>(&X [(m0 + lr)      * ND + k0 + lq * 4]);
        float4 x1 = *reinterpret_cast<const float4*>(&X [(m0 + 64 + lr) * ND + k0 + lq * 4]);
        float4 w0 = *reinterpret_cast<const float4*>(&Wb[(n0 + lr)      * ND + k0 + lq * 4]);
        float4 w1 = *reinterpret_cast<const float4*>(&Wb[(n0 + 64 + lr) * ND + k0 + lq * 4]);
        __syncthreads();
        Xs[lq * 4 + 0][lr] = x0.x; Xs[lq * 4 + 1][lr] = x0.y;
        Xs[lq * 4 + 2][lr] = x0.z; Xs[lq * 4 + 3][lr] = x0.w;
        Xs[lq * 4 + 0][64 + lr] = x1.x; Xs[lq * 4 + 1][64 + lr] = x1.y;
        Xs[lq * 4 + 2][64 + lr] = x1.z; Xs[lq * 4 + 3][64 + lr] = x1.w;
        Wt[lq * 4 + 0][lr] = w0.x; Wt[lq * 4 + 1][lr] = w0.y;
        Wt[lq * 4 + 2][lr] = w0.z; Wt[lq * 4 + 3][lr] = w0.w;
        Wt[lq * 4 + 0][64 + lr] = w1.x; Wt[lq * 4 + 1][64 + lr] = w1.y;
        Wt[lq * 4 + 2][64 + lr] = w1.z; Wt[lq * 4 + 3][64 + lr] = w1.w;
        __syncthreads();
#pragma unroll
        for (int kk = 0; kk < 16; kk++) {
            float4 a0 = *reinterpret_cast<const float4*>(&Xs[kk][ty * 8]);
            float4 a1 = *reinterpret_cast<const float4*>(&Xs[kk][ty * 8 + 4]);
            float4 b0 = *reinterpret_cast<const float4*>(&Wt[kk][tx * 8]);
            float4 b1 = *reinterpret_cast<const float4*>(&Wt[kk][tx * 8 + 4]);
            float av[8] = {a0.x, a0.y, a0.z, a0.w, a1.x, a1.y, a1.z, a1.w};
            float bv[8] = {b0.x, b0.y, b0.z, b0.w, b1.x, b1.y, b1.z, b1.w};
#pragma unroll
            for (int r = 0; r < 8; r++)
#pragma unroll
                for (int c = 0; c < 8; c++)
                    acc[r][c] = fmaf(av[r], bv[c], acc[r][c]);
        }
    }
#pragma unroll
    for (int r = 0; r < 8; r++) {
        float4 o0 = make_float4(acc[r][0], acc[r][1], acc[r][2], acc[r][3]);
        float4 o1 = make_float4(acc[r][4], acc[r][5], acc[r][6], acc[r][7]);
        *reinterpret_cast<float4*>(&g_uin[(m0 + ty * 8 + r) * NH + n0 + tx * 8])     = o0;
        *reinterpret_cast<float4*>(&g_uin[(m0 + ty * 8 + r) * NH + n0 + tx * 8 + 4]) = o1;
    }
}

// ---------------- kernel 3: inv_norm pre-pass (register-resident A) ---------
__global__ __launch_bounds__(256, 3) void norm_kernel(const float* __restrict__ A)
{
    int jbase = blockIdx.x * 8;
    int w = threadIdx.x >> 5, l = threadIdx.x & 31;
    int j = jbase + w;

    float4 Ar[8];
#pragma unroll
    for (int r = 0; r < 8; r++)
        Ar[r] = reinterpret_cast<const float4*>(A)[(l + 32 * r) * NH + j];

    const int rows_per_blk = NROWS / 64;       // 256
    const int row0 = blockIdx.y * rows_per_blk;
    const float ninv = -1.0f / 1.2f;

    for (int row = row0; row < row0 + rows_per_blk; row += 2) {
        float4 sA = __ldg(reinterpret_cast<const float4*>(&g_sel[row * NK]));
        float4 sB = __ldg(reinterpret_cast<const float4*>(&g_sel[(row + 1) * NK]));
        float accA = 0.f, accB = 0.f;
#pragma unroll
        for (int r = 0; r < 8; r++) {
            float a = fmaf(sA.x, Ar[r].x, fmaf(sA.y, Ar[r].y,
                      fmaf(sA.z, Ar[r].z, sA.w * Ar[r].w)));
            float b = fmaf(sB.x, Ar[r].x, fmaf(sB.y, Ar[r].y,
                      fmaf(sB.z, Ar[r].z, sB.w * Ar[r].w)));
            accA += fast_ex2(0.6f * fast_lg2(a * a));
            accB += fast_ex2(0.6f * fast_lg2(b * b));
        }
#pragma unroll
        for (int o = 16; o > 0; o >>= 1) {
            accA += __shfl_xor_sync(0xffffffffu, accA, o);
            accB += __shfl_xor_sync(0xffffffffu, accB, o);
        }
        if (l == 0) {
            g_invn[row * NH + j]       = fast_ex2(fast_lg2(accA) * ninv);
            g_invn[(row + 1) * NH + j] = fast_ex2(fast_lg2(accB) * ninv);
        }
    }
}

// ---------------- kernel 4: scan, 2 batches/cluster, PARALLEL tails ---------
// R7 protocol, but warp0 owns batch0's state/tail and warp1 owns batch1's,
// running concurrently (R7 serialized both through warp0). Per iteration:
//   warps 0,1 write y_sm[wid]; sync; all warps matvec+store both batches;
//   amix recompute; warps 0,1 each: prefetch (inv,u for t+1), wait own mbar,
//   post own expect(t+2), consume own pbuf, store out, update h.
__global__ __launch_bounds__(512, 1) __cluster_dims__(8, 1, 1)
void scan_kernel(const float* __restrict__ A, float* __restrict__ out)
{
    __shared__ float y_sm[2][32];
    __shared__ float pbuf[2][2][8][32];                     // [parity][batch][src][row]
    __shared__ __align__(8) unsigned long long mbar[2][2];  // [parity][batch]

    int tid = threadIdx.x;
    uint32_t rank;
    asm("mov.u32 %0, %%cluster_ctarank;" : "=r"(rank));
    int c = blockIdx.x >> 3;                 // cluster id -> batches 2c, 2c+1
    int jbase = (int)rank * 32;
    int i = tid >> 1, half = tid & 1;
    int wid = tid >> 5, lane = tid & 31;

    float4 Areg[16];
#pragma unroll
    for (int q = 0; q < 16; q++)
        Areg[q] = reinterpret_cast<const float4*>(A)[i * NH + jbase + half * 16 + q];

    uint32_t mbar_s = smem_u32(mbar);
    if (tid == 0) {
#pragma unroll
        for (int m = 0; m < 4; m++)
            asm volatile("mbarrier.init.shared.b64 [%0], 1;"
                         :: "r"(mbar_s + m * 8) : "memory");
    }
    __syncthreads();
    if (tid == 0) {
#pragma unroll
        for (int m = 0; m < 4; m++)
            asm volatile("mbarrier.arrive.expect_tx.shared.b64 _, [%0], 1024;"
                         :: "r"(mbar_s + m * 8) : "memory");
    }
    __syncthreads();
    asm volatile("barrier.cluster.arrive.aligned;" ::: "memory");
    asm volatile("barrier.cluster.wait.aligned;"  ::: "memory");

    uint32_t dst = (uint32_t)(i >> 5);
    uint32_t lbase = smem_u32(pbuf) + (rank * 32u + (uint32_t)(i & 31)) * 4u;
    uint32_t raddr = mapa_u32(lbase, dst);   // parity stride 2048B, batch stride 1024B
    uint32_t rmbar = mapa_u32(mbar_s, dst);  // parity stride 16B,   batch stride 8B

    const int row0base = (2 * c) * NL;
    const int row1base = (2 * c + 1) * NL;

    float4 s0 = __ldg(reinterpret_cast<const float4*>(&g_sel[row0base * NK]));
    float4 s1 = __ldg(reinterpret_cast<const float4*>(&g_sel[row1base * NK]));

    // per-warp batch ownership: warp0 -> batch0, warp1 -> batch1
    const int myrowbase = (wid == 0) ? row0base : row1base;
    float inv_c = 0.f, u_c = 0.f, h_c = 0.f;
    if (wid < 2) {
        inv_c = __ldg(&g_invn[myrowbase * NH + jbase + lane]);
        u_c   = __ldg(&g_uin [myrowbase * NH + jbase + lane]);
    }

    float amix0[16], amix1[16];
#pragma unroll
    for (int q = 0; q < 16; q++) {
        amix0[q] = fmaf(s0.x, Areg[q].x, fmaf(s0.y, Areg[q].y,
                   fmaf(s0.z, Areg[q].z, s0.w * Areg[q].w)));
        amix1[q] = fmaf(s1.x, Areg[q].x, fmaf(s1.y, Areg[q].y,
                   fmaf(s1.z, Areg[q].z, s1.w * Areg[q].w)));
    }

    for (int t = 0; t < NL; t++) {
        if (wid < 2) y_sm[wid][lane] = h_c * inv_c;
        __syncthreads();

        const int d = (t < NL - 1) ? 1 : 0;
        float4 s_n0 = __ldg(reinterpret_cast<const float4*>(&g_sel[(row0base + t + d) * NK]));
        float4 s_n1 = __ldg(reinterpret_cast<const float4*>(&g_sel[(row1base + t + d) * NK]));
        float inv_n = 0.f, u_n = 0.f;
        if (wid < 2) {
            inv_n = __ldg(&g_invn[(myrowbase + t + d) * NH + jbase + lane]);
            u_n   = __ldg(&g_uin [(myrowbase + t + d) * NH + jbase + lane]);
        }

        const uint32_t poff = (uint32_t)(t & 1);

        // ---- batch 0: matvec + store ----
        {
            float a0 = 0.f, a1 = 0.f;
#pragma unroll
            for (int q = 0; q < 16; q += 2) {
                a0 = fmaf(amix0[q],     y_sm[0][half * 16 + q],     a0);
                a1 = fmaf(amix0[q + 1], y_sm[0][half * 16 + q + 1], a1);
            }
            float acc = a0 + a1;
            acc += __shfl_xor_sync(0xffffffffu, acc, 1);
            if (half == 0) {
                asm volatile(
                    "st.async.shared::cluster.mbarrier::complete_tx::bytes.b32 [%0], %1, [%2];"
                    :: "r"(raddr + poff * 2048u), "r"(__float_as_uint(acc)),
                       "r"(rmbar + poff * 16u) : "memory");
            }
        }
        // ---- batch 1: matvec + store (hides batch0 flight) ----
        {
            float a0 = 0.f, a1 = 0.f;
#pragma unroll
            for (int q = 0; q < 16; q += 2) {
                a0 = fmaf(amix1[q],     y_sm[1][half * 16 + q],     a0);
                a1 = fmaf(amix1[q + 1], y_sm[1][half * 16 + q + 1], a1);
            }
            float acc = a0 + a1;
            acc += __shfl_xor_sync(0xffffffffu, acc, 1);
            if (half == 0) {
                asm volatile(
                    "st.async.shared::cluster.mbarrier::complete_tx::bytes.b32 [%0], %1, [%2];"
                    :: "r"(raddr + poff * 2048u + 1024u), "r"(__float_as_uint(acc)),
                       "r"(rmbar + poff * 16u + 8u) : "memory");
            }
        }

        // hide DSMEM flight: amix for t+1, both batches
#pragma unroll
        for (int q = 0; q < 16; q++) {
            amix0[q] = fmaf(s_n0.x, Areg[q].x, fmaf(s_n0.y, Areg[q].y,
                       fmaf(s_n0.z, Areg[q].z, s_n0.w * Areg[q].w)));
            amix1[q] = fmaf(s_n1.x, Areg[q].x, fmaf(s_n1.y, Areg[q].y,
                       fmaf(s_n1.z, Areg[q].z, s_n1.w * Areg[q].w)));
        }

        // ---- parallel tails: warp0 consumes batch0, warp1 consumes batch1 --
        if (wid < 2) {
            const uint32_t ph = (uint32_t)((t >> 1) & 1);
            const uint32_t mb = mbar_s + poff * 16u + (uint32_t)wid * 8u;
            mbar_wait(mb, ph);
            if (lane == 0 && t + 2 < NL)
                asm volatile("mbarrier.arrive.expect_tx.shared.b64 _, [%0], 1024;"
                             :: "r"(mb) : "memory");
            const float* pb = &pbuf[poff][wid][0][lane];
            float b0 = pb[0]   + pb[32];
            float b1 = pb[64]  + pb[96];
            float b2 = pb[128] + pb[160];
            float b3 = pb[192] + pb[224];
            float hv = u_c + ((b0 + b1) + (b2 + b3));
            out[(myrowbase + t) * NH + jbase + lane] = hv;
            h_c = hv; inv_c = inv_n; u_c = u_n;
        }
        s0 = s_n0; s1 = s_n1;   // keep (unused after amix, cheap)
    }

    asm volatile("barrier.cluster.arrive.aligned;" ::: "memory");
    asm volatile("barrier.cluster.wait.aligned;"  ::: "memory");
}

// ---------------- launch ----------------------------------------------------
extern "C" void kernel_launch(void* const* d_in, const int* in_sizes, int n_in,
                              void* d_out, int out_size)
{
    const float* x     = (const float*)d_in[0];   // (16,1024,512)
    const float* Wsel  = (const float*)d_in[1];   // (4,512)
    const float* bsel  = (const float*)d_in[2];   // (4,)
    const float* Wb    = (const float*)d_in[3];   // (256,512)
    const float* Adict = (const float*)d_in[4];   // (256,256,4)
    float* out = (float*)d_out;                   // (16,1024,256)

    sel_kernel<<<NROWS / 8, 256>>>(x, Wsel, bsel);
    uin_kernel<<<dim3(NROWS / 128, NH / 128), 256>>>(x, Wb);
    norm_kernel<<<dim3(32, 64), 256>>>(Adict);
    scan_kernel<<<(NB / 2) * 8, 512>>>(Adict, out);
}